// round 6
// baseline (speedup 1.0000x reference)
#include <cuda_runtime.h>

#define N_NODES 50000
#define N_EDGES 800000
#define CH 128
#define OUT_CH 64

// ---- persistent device scratch (no allocation allowed) ----
__device__ int   g_is64;
__device__ int   g_deg[N_NODES];
__device__ float g_dinv[N_NODES];
__device__ int   g_rowptr[N_NODES + 1];
__device__ int   g_fill[N_NODES];
__device__ int   g_csr[N_EDGES];
__device__ __align__(16) float g_h1[(size_t)N_NODES * CH];
__device__ __align__(16) float g_hidden[(size_t)N_NODES * CH];
__device__ __align__(16) float g_h23[(size_t)N_NODES * CH];
__device__ __align__(16) float g_wc[CH * CH];

// read edge index element i (source block: i in [0,E); target block: i in [E,2E))
__device__ __forceinline__ int edge_at(const void* p, int i) {
    if (g_is64) {
        long long v = ((const long long*)p)[i];
        return (int)v;
    }
    return ((const int*)p)[i];
}

// ---------------------------------------------------------------------------
// Detect whether edge_index is int64 or int32 on device. Reading the first
// 256 int64 words (2KB) is safe under either layout. If the buffer is int32,
// the high 32 bits of some word will be a non-zero node index.
__global__ void k_detect(const void* ei) {
    if (threadIdx.x == 0) {
        const long long* p = (const long long*)ei;
        int ok64 = 1;
        for (int i = 0; i < 256; i++) {
            long long v = p[i];
            if (v < 0 || v >= N_NODES) { ok64 = 0; break; }
        }
        g_is64 = ok64;
    }
}

__global__ void k_init() {
    int i = blockIdx.x * blockDim.x + threadIdx.x;
    if (i < N_NODES) { g_deg[i] = 1; g_fill[i] = 0; }
}

__global__ void k_deg(const void* __restrict__ ei) {
    int e = blockIdx.x * blockDim.x + threadIdx.x;
    if (e < N_EDGES) {
        int c = edge_at(ei, N_EDGES + e);   // target node
        if ((unsigned)c < N_NODES) atomicAdd(&g_deg[c], 1);
    }
}

__global__ void k_dinv() {
    int i = blockIdx.x * blockDim.x + threadIdx.x;
    if (i < N_NODES) g_dinv[i] = rsqrtf((float)g_deg[i]);
}

// single-block exclusive scan of (deg-1) -> rowptr
__global__ void k_scan() {
    __shared__ int sh[1024];
    __shared__ int s_off;
    int t = threadIdx.x;
    if (t == 0) s_off = 0;
    __syncthreads();
    for (int base = 0; base < N_NODES; base += 1024) {
        int i = base + t;
        int v = (i < N_NODES) ? (g_deg[i] - 1) : 0;
        sh[t] = v;
        __syncthreads();
        #pragma unroll
        for (int d = 1; d < 1024; d <<= 1) {
            int add = (t >= d) ? sh[t - d] : 0;
            __syncthreads();
            sh[t] += add;
            __syncthreads();
        }
        if (i < N_NODES) g_rowptr[i] = s_off + sh[t] - v;
        __syncthreads();
        if (t == 0) s_off += sh[1023];
        __syncthreads();
    }
    if (t == 0) g_rowptr[N_NODES] = s_off;
}

__global__ void k_fill(const void* __restrict__ ei) {
    int e = blockIdx.x * blockDim.x + threadIdx.x;
    if (e < N_EDGES) {
        int s = edge_at(ei, e);             // source node
        int c = edge_at(ei, N_EDGES + e);   // target node
        if ((unsigned)c < N_NODES && (unsigned)s < N_NODES) {
            int pos = g_rowptr[c] + atomicAdd(&g_fill[c], 1);
            if ((unsigned)pos < N_EDGES) g_csr[pos] = s;
        }
    }
}

__global__ void k_pack(const float* __restrict__ W2, const float* __restrict__ W3) {
    int i = blockIdx.x * blockDim.x + threadIdx.x;
    if (i < CH * CH) {
        int k = i >> 7, c = i & 127;
        g_wc[i] = (c < OUT_CH) ? W2[k * OUT_CH + c] : W3[k * OUT_CH + (c - OUT_CH)];
    }
}

// ---------------------------------------------------------------------------
// C[M,128] = A[M,128] @ B[128,128], classic 128x128 tile, 8x8 per thread
__device__ __forceinline__ void gemm_body(const float* __restrict__ A,
                                          const float* __restrict__ B,
                                          float* __restrict__ C, int M) {
    __shared__ float As[16][128];
    __shared__ float Bs[16][128];
    int tid = threadIdx.x;                 // 256 threads
    int tm = (tid >> 4) << 3;              // 0..120
    int tn = (tid & 15) << 3;              // 0..120
    int m0 = blockIdx.x * 128;

    float acc[8][8];
    #pragma unroll
    for (int i = 0; i < 8; i++)
        #pragma unroll
        for (int j = 0; j < 8; j++) acc[i][j] = 0.f;

    for (int k0 = 0; k0 < CH; k0 += 16) {
        #pragma unroll
        for (int l = 0; l < 2; l++) {
            int idx = tid + l * 256;       // 0..511
            int r = idx >> 2;              // 0..127
            int kq = (idx & 3) << 2;       // 0,4,8,12
            float4 v = make_float4(0.f, 0.f, 0.f, 0.f);
            if (m0 + r < M) v = *(const float4*)(A + (size_t)(m0 + r) * CH + k0 + kq);
            As[kq + 0][r] = v.x; As[kq + 1][r] = v.y;
            As[kq + 2][r] = v.z; As[kq + 3][r] = v.w;
        }
        #pragma unroll
        for (int l = 0; l < 2; l++) {
            int idx = tid + l * 256;
            int r = idx >> 5;              // 0..15
            int cq = (idx & 31) << 2;      // 0..124
            *(float4*)&Bs[r][cq] = *(const float4*)(B + (size_t)(k0 + r) * CH + cq);
        }
        __syncthreads();
        #pragma unroll
        for (int k = 0; k < 16; k++) {
            float a[8], b[8];
            #pragma unroll
            for (int i = 0; i < 8; i++) a[i] = As[k][tm + i];
            #pragma unroll
            for (int j = 0; j < 8; j++) b[j] = Bs[k][tn + j];
            #pragma unroll
            for (int i = 0; i < 8; i++)
                #pragma unroll
                for (int j = 0; j < 8; j++) acc[i][j] = fmaf(a[i], b[j], acc[i][j]);
        }
        __syncthreads();
    }
    #pragma unroll
    for (int i = 0; i < 8; i++) {
        int r = m0 + tm + i;
        if (r < M) {
            #pragma unroll
            for (int j = 0; j < 8; j += 4)
                *(float4*)(C + (size_t)r * CH + tn + j) =
                    make_float4(acc[i][j], acc[i][j + 1], acc[i][j + 2], acc[i][j + 3]);
        }
    }
}

__global__ void k_gemm1(const float* __restrict__ A, const float* __restrict__ B) {
    gemm_body(A, B, g_h1, N_NODES);
}

__global__ void k_gemm2() {
    gemm_body(g_hidden, g_wc, g_h23, N_NODES);
}

// ---------------------------------------------------------------------------
// warp-per-node gather aggregation, layer 1: hidden = relu(agg(h1)*norm + b1)
__global__ void k_gather1(const float* __restrict__ b1) {
    int gtid = blockIdx.x * blockDim.x + threadIdx.x;
    int node = gtid >> 5;
    int lane = gtid & 31;
    if (node >= N_NODES) return;
    int start = g_rowptr[node], end = g_rowptr[node + 1];
    float4 acc = make_float4(0.f, 0.f, 0.f, 0.f);
    const float* h = g_h1;
    for (int j = start; j < end; j++) {
        int s = __ldg(&g_csr[j]);
        float w = __ldg(&g_dinv[s]);
        float4 hv = *(const float4*)(h + (size_t)s * CH + lane * 4);
        acc.x = fmaf(w, hv.x, acc.x);
        acc.y = fmaf(w, hv.y, acc.y);
        acc.z = fmaf(w, hv.z, acc.z);
        acc.w = fmaf(w, hv.w, acc.w);
    }
    float me = g_dinv[node];
    float m2 = me * me;
    float4 self = *(const float4*)(h + (size_t)node * CH + lane * 4);
    float4 bb   = *(const float4*)(b1 + lane * 4);
    float4 o;
    o.x = fmaxf(fmaf(acc.x, me, fmaf(self.x, m2, bb.x)), 0.f);
    o.y = fmaxf(fmaf(acc.y, me, fmaf(self.y, m2, bb.y)), 0.f);
    o.z = fmaxf(fmaf(acc.z, me, fmaf(self.z, m2, bb.z)), 0.f);
    o.w = fmaxf(fmaf(acc.w, me, fmaf(self.w, m2, bb.w)), 0.f);
    *(float4*)(g_hidden + (size_t)node * CH + lane * 4) = o;
}

// layer 2: split channels 0-63 -> x1 (+b2), 64-127 -> x2 (+b3)
__global__ void k_gather2(const float* __restrict__ b2, const float* __restrict__ b3,
                          float* __restrict__ out) {
    int gtid = blockIdx.x * blockDim.x + threadIdx.x;
    int node = gtid >> 5;
    int lane = gtid & 31;
    if (node >= N_NODES) return;
    int start = g_rowptr[node], end = g_rowptr[node + 1];
    float4 acc = make_float4(0.f, 0.f, 0.f, 0.f);
    const float* h = g_h23;
    for (int j = start; j < end; j++) {
        int s = __ldg(&g_csr[j]);
        float w = __ldg(&g_dinv[s]);
        float4 hv = *(const float4*)(h + (size_t)s * CH + lane * 4);
        acc.x = fmaf(w, hv.x, acc.x);
        acc.y = fmaf(w, hv.y, acc.y);
        acc.z = fmaf(w, hv.z, acc.z);
        acc.w = fmaf(w, hv.w, acc.w);
    }
    float me = g_dinv[node];
    float m2 = me * me;
    float4 self = *(const float4*)(h + (size_t)node * CH + lane * 4);
    const float* bias = (lane < 16) ? (b2 + lane * 4) : (b3 + (lane - 16) * 4);
    float4 bb = *(const float4*)bias;
    float4 o;
    o.x = fmaxf(fmaf(acc.x, me, fmaf(self.x, m2, bb.x)), 0.f);
    o.y = fmaxf(fmaf(acc.y, me, fmaf(self.y, m2, bb.y)), 0.f);
    o.z = fmaxf(fmaf(acc.z, me, fmaf(self.z, m2, bb.z)), 0.f);
    o.w = fmaxf(fmaf(acc.w, me, fmaf(self.w, m2, bb.w)), 0.f);
    float* dst = (lane < 16)
        ? (out + (size_t)node * OUT_CH + lane * 4)
        : (out + (size_t)N_NODES * OUT_CH + (size_t)node * OUT_CH + (lane - 16) * 4);
    *(float4*)dst = o;
}

// ---------------------------------------------------------------------------
extern "C" void kernel_launch(void* const* d_in, const int* in_sizes, int n_in,
                              void* d_out, int out_size) {
    const float* x  = (const float*)d_in[0];
    const void*  ei = d_in[1];
    const float* W1 = (const float*)d_in[2];
    const float* b1 = (const float*)d_in[3];
    const float* W2 = (const float*)d_in[4];
    const float* b2 = (const float*)d_in[5];
    const float* W3 = (const float*)d_in[6];
    const float* b3 = (const float*)d_in[7];
    float* out = (float*)d_out;

    k_detect<<<1, 32>>>(ei);
    k_init<<<(N_NODES + 255) / 256, 256>>>();
    k_deg<<<(N_EDGES + 255) / 256, 256>>>(ei);
    k_dinv<<<(N_NODES + 255) / 256, 256>>>();
    k_scan<<<1, 1024>>>();
    k_fill<<<(N_EDGES + 255) / 256, 256>>>(ei);

    k_gemm1<<<(N_NODES + 127) / 128, 256>>>(x, W1);
    k_pack<<<(CH * CH + 255) / 256, 256>>>(W2, W3);
    k_gather1<<<(N_NODES * 32 + 255) / 256, 256>>>(b1);

    k_gemm2<<<(N_NODES + 127) / 128, 256>>>();
    k_gather2<<<(N_NODES * 32 + 255) / 256, 256>>>(b2, b3, out);
}

// round 7
// speedup vs baseline: 1.2596x; 1.2596x over previous
#include <cuda_runtime.h>

#define N_NODES 50000
#define N_EDGES 800000
#define CH 128
#define OUT_CH 64
#define SCAN_B 1024
#define SCAN_NB ((N_NODES + SCAN_B - 1) / SCAN_B)   // 49

// ---- persistent device scratch (no allocation allowed) ----
__device__ int   g_is64;
__device__ int   g_deg[N_NODES];
__device__ float g_dinv[N_NODES];
__device__ int   g_rowptr[N_NODES + 1];
__device__ int   g_fill[N_NODES];
__device__ int   g_bsum[64];
__device__ int   g_csr[N_EDGES];
__device__ __align__(16) float g_h1[(size_t)N_NODES * CH];
__device__ __align__(16) float g_hidden[(size_t)N_NODES * CH];
__device__ __align__(16) float g_h23[(size_t)N_NODES * CH];
__device__ __align__(16) float g_wc[CH * CH];

__device__ __forceinline__ int edge_at(const void* p, int i) {
    if (g_is64) return (int)(((const long long*)p)[i]);
    return ((const int*)p)[i];
}

// ---------------------------------------------------------------------------
// fused: deg/fill init + dtype detect + W2|W3 pack
__global__ void k_pre(const void* ei, const float* __restrict__ W2,
                      const float* __restrict__ W3) {
    int i = blockIdx.x * blockDim.x + threadIdx.x;
    if (i < N_NODES) { g_deg[i] = 1; g_fill[i] = 0; }
    if (i < CH * CH) {
        int k = i >> 7, c = i & 127;
        g_wc[i] = (c < OUT_CH) ? W2[k * OUT_CH + c] : W3[k * OUT_CH + (c - OUT_CH)];
    }
    if (i == 0) {
        const long long* p = (const long long*)ei;
        int ok64 = 1;
        for (int t = 0; t < 256; t++) {
            long long v = p[t];
            if (v < 0 || v >= N_NODES) { ok64 = 0; break; }
        }
        g_is64 = ok64;
    }
}

__global__ void k_deg(const void* __restrict__ ei) {
    int e = blockIdx.x * blockDim.x + threadIdx.x;
    if (e < N_EDGES) {
        int c = edge_at(ei, N_EDGES + e);
        if ((unsigned)c < N_NODES) atomicAdd(&g_deg[c], 1);
    }
}

// scan pass 1: per-block exclusive scan of (deg-1), block sums, fused dinv
__global__ void k_scan1() {
    __shared__ int wsum[32];
    int t = threadIdx.x;
    int i = blockIdx.x * SCAN_B + t;
    int lane = t & 31, wid = t >> 5;
    int v = 0;
    if (i < N_NODES) {
        int d = g_deg[i];
        v = d - 1;
        g_dinv[i] = rsqrtf((float)d);
    }
    int x = v;
    #pragma unroll
    for (int d = 1; d < 32; d <<= 1) {
        int y = __shfl_up_sync(0xffffffffu, x, d);
        if (lane >= d) x += y;
    }
    if (lane == 31) wsum[wid] = x;
    __syncthreads();
    if (wid == 0) {
        int y = wsum[lane];
        #pragma unroll
        for (int d = 1; d < 32; d <<= 1) {
            int z = __shfl_up_sync(0xffffffffu, y, d);
            if (lane >= d) y += z;
        }
        wsum[lane] = y;                       // inclusive over warps
    }
    __syncthreads();
    int base = (wid > 0) ? wsum[wid - 1] : 0;
    if (i < N_NODES) g_rowptr[i] = base + x - v;   // block-local exclusive
    if (t == SCAN_B - 1) g_bsum[blockIdx.x] = wsum[31];
}

// scan pass 2: exclusive scan of 49 block sums (2 warps)
__global__ void k_scan2() {
    int t = threadIdx.x;                      // 64 threads
    int lane = t & 31, w = t >> 5;
    int v = (t < SCAN_NB) ? g_bsum[t] : 0;
    int x = v;
    #pragma unroll
    for (int d = 1; d < 32; d <<= 1) {
        int y = __shfl_up_sync(0xffffffffu, x, d);
        if (lane >= d) x += y;
    }
    __shared__ int s0;
    if (w == 0 && lane == 31) s0 = x;
    __syncthreads();
    if (w == 1) x += s0;
    if (t < SCAN_NB) g_bsum[t] = x - v;       // exclusive
}

// scan pass 3: add block offsets; total is N_EDGES by construction
__global__ void k_scan3() {
    int i = blockIdx.x * SCAN_B + threadIdx.x;
    if (i < N_NODES) g_rowptr[i] += g_bsum[blockIdx.x];
    if (i == 0) g_rowptr[N_NODES] = N_EDGES;
}

__global__ void k_fill(const void* __restrict__ ei) {
    int e = blockIdx.x * blockDim.x + threadIdx.x;
    if (e < N_EDGES) {
        int s = edge_at(ei, e);
        int c = edge_at(ei, N_EDGES + e);
        if ((unsigned)c < N_NODES && (unsigned)s < N_NODES) {
            int pos = g_rowptr[c] + atomicAdd(&g_fill[c], 1);
            if ((unsigned)pos < N_EDGES) g_csr[pos] = s;
        }
    }
}

// ---------------------------------------------------------------------------
// C[M,128] = A[M,128] @ B[128,128], 128x128 tile, 8x8 per thread
__device__ __forceinline__ void gemm_body(const float* __restrict__ A,
                                          const float* __restrict__ B,
                                          float* __restrict__ C, int M) {
    __shared__ float As[16][128];
    __shared__ float Bs[16][128];
    int tid = threadIdx.x;                 // 256 threads
    int tm = (tid >> 4) << 3;
    int tn = (tid & 15) << 3;
    int m0 = blockIdx.x * 128;

    float acc[8][8];
    #pragma unroll
    for (int i = 0; i < 8; i++)
        #pragma unroll
        for (int j = 0; j < 8; j++) acc[i][j] = 0.f;

    for (int k0 = 0; k0 < CH; k0 += 16) {
        #pragma unroll
        for (int l = 0; l < 2; l++) {
            int idx = tid + l * 256;
            int r = idx >> 2;
            int kq = (idx & 3) << 2;
            float4 v = make_float4(0.f, 0.f, 0.f, 0.f);
            if (m0 + r < M) v = *(const float4*)(A + (size_t)(m0 + r) * CH + k0 + kq);
            As[kq + 0][r] = v.x; As[kq + 1][r] = v.y;
            As[kq + 2][r] = v.z; As[kq + 3][r] = v.w;
        }
        #pragma unroll
        for (int l = 0; l < 2; l++) {
            int idx = tid + l * 256;
            int r = idx >> 5;
            int cq = (idx & 31) << 2;
            *(float4*)&Bs[r][cq] = *(const float4*)(B + (size_t)(k0 + r) * CH + cq);
        }
        __syncthreads();
        #pragma unroll
        for (int k = 0; k < 16; k++) {
            float a[8], b[8];
            #pragma unroll
            for (int i = 0; i < 8; i++) a[i] = As[k][tm + i];
            #pragma unroll
            for (int j = 0; j < 8; j++) b[j] = Bs[k][tn + j];
            #pragma unroll
            for (int i = 0; i < 8; i++)
                #pragma unroll
                for (int j = 0; j < 8; j++) acc[i][j] = fmaf(a[i], b[j], acc[i][j]);
        }
        __syncthreads();
    }
    #pragma unroll
    for (int i = 0; i < 8; i++) {
        int r = m0 + tm + i;
        if (r < M) {
            #pragma unroll
            for (int j = 0; j < 8; j += 4)
                *(float4*)(C + (size_t)r * CH + tn + j) =
                    make_float4(acc[i][j], acc[i][j + 1], acc[i][j + 2], acc[i][j + 3]);
        }
    }
}

__global__ void k_gemm1(const float* __restrict__ A, const float* __restrict__ B) {
    gemm_body(A, B, g_h1, N_NODES);
}
__global__ void k_gemm2() {
    gemm_body(g_hidden, g_wc, g_h23, N_NODES);
}

// ---------------------------------------------------------------------------
// warp-per-node gather, unroll-2 for MLP
__device__ __forceinline__ float4 gather_row(const float* __restrict__ h, int node,
                                             int lane) {
    int start = __ldg(&g_rowptr[node]);
    int end   = __ldg(&g_rowptr[node + 1]);
    float4 a0 = make_float4(0.f, 0.f, 0.f, 0.f);
    float4 a1 = make_float4(0.f, 0.f, 0.f, 0.f);
    int j = start;
    for (; j + 1 < end; j += 2) {
        int s0 = __ldg(&g_csr[j]);
        int s1 = __ldg(&g_csr[j + 1]);
        float w0 = __ldg(&g_dinv[s0]);
        float w1 = __ldg(&g_dinv[s1]);
        float4 v0 = *(const float4*)(h + (size_t)s0 * CH + lane * 4);
        float4 v1 = *(const float4*)(h + (size_t)s1 * CH + lane * 4);
        a0.x = fmaf(w0, v0.x, a0.x); a1.x = fmaf(w1, v1.x, a1.x);
        a0.y = fmaf(w0, v0.y, a0.y); a1.y = fmaf(w1, v1.y, a1.y);
        a0.z = fmaf(w0, v0.z, a0.z); a1.z = fmaf(w1, v1.z, a1.z);
        a0.w = fmaf(w0, v0.w, a0.w); a1.w = fmaf(w1, v1.w, a1.w);
    }
    if (j < end) {
        int s0 = __ldg(&g_csr[j]);
        float w0 = __ldg(&g_dinv[s0]);
        float4 v0 = *(const float4*)(h + (size_t)s0 * CH + lane * 4);
        a0.x = fmaf(w0, v0.x, a0.x);
        a0.y = fmaf(w0, v0.y, a0.y);
        a0.z = fmaf(w0, v0.z, a0.z);
        a0.w = fmaf(w0, v0.w, a0.w);
    }
    a0.x += a1.x; a0.y += a1.y; a0.z += a1.z; a0.w += a1.w;
    return a0;
}

__global__ void k_gather1(const float* __restrict__ b1) {
    int gtid = blockIdx.x * blockDim.x + threadIdx.x;
    int node = gtid >> 5;
    int lane = gtid & 31;
    if (node >= N_NODES) return;
    float4 acc = gather_row(g_h1, node, lane);
    float me = __ldg(&g_dinv[node]);
    float m2 = me * me;
    float4 self = *(const float4*)(g_h1 + (size_t)node * CH + lane * 4);
    float4 bb   = *(const float4*)(b1 + lane * 4);
    float4 o;
    o.x = fmaxf(fmaf(acc.x, me, fmaf(self.x, m2, bb.x)), 0.f);
    o.y = fmaxf(fmaf(acc.y, me, fmaf(self.y, m2, bb.y)), 0.f);
    o.z = fmaxf(fmaf(acc.z, me, fmaf(self.z, m2, bb.z)), 0.f);
    o.w = fmaxf(fmaf(acc.w, me, fmaf(self.w, m2, bb.w)), 0.f);
    *(float4*)(g_hidden + (size_t)node * CH + lane * 4) = o;
}

__global__ void k_gather2(const float* __restrict__ b2, const float* __restrict__ b3,
                          float* __restrict__ out) {
    int gtid = blockIdx.x * blockDim.x + threadIdx.x;
    int node = gtid >> 5;
    int lane = gtid & 31;
    if (node >= N_NODES) return;
    float4 acc = gather_row(g_h23, node, lane);
    float me = __ldg(&g_dinv[node]);
    float m2 = me * me;
    float4 self = *(const float4*)(g_h23 + (size_t)node * CH + lane * 4);
    const float* bias = (lane < 16) ? (b2 + lane * 4) : (b3 + (lane - 16) * 4);
    float4 bb = *(const float4*)bias;
    float4 o;
    o.x = fmaxf(fmaf(acc.x, me, fmaf(self.x, m2, bb.x)), 0.f);
    o.y = fmaxf(fmaf(acc.y, me, fmaf(self.y, m2, bb.y)), 0.f);
    o.z = fmaxf(fmaf(acc.z, me, fmaf(self.z, m2, bb.z)), 0.f);
    o.w = fmaxf(fmaf(acc.w, me, fmaf(self.w, m2, bb.w)), 0.f);
    float* dst = (lane < 16)
        ? (out + (size_t)node * OUT_CH + lane * 4)
        : (out + (size_t)N_NODES * OUT_CH + (size_t)node * OUT_CH + (lane - 16) * 4);
    *(float4*)dst = o;
}

// ---------------------------------------------------------------------------
extern "C" void kernel_launch(void* const* d_in, const int* in_sizes, int n_in,
                              void* d_out, int out_size) {
    const float* x  = (const float*)d_in[0];
    const void*  ei = d_in[1];
    const float* W1 = (const float*)d_in[2];
    const float* b1 = (const float*)d_in[3];
    const float* W2 = (const float*)d_in[4];
    const float* b2 = (const float*)d_in[5];
    const float* W3 = (const float*)d_in[6];
    const float* b3 = (const float*)d_in[7];
    float* out = (float*)d_out;

    k_pre<<<(N_NODES + 255) / 256, 256>>>(ei, W2, W3);
    k_deg<<<(N_EDGES + 255) / 256, 256>>>(ei);
    k_scan1<<<SCAN_NB, SCAN_B>>>();
    k_scan2<<<1, 64>>>();
    k_scan3<<<SCAN_NB, SCAN_B>>>();
    k_fill<<<(N_EDGES + 255) / 256, 256>>>(ei);

    k_gemm1<<<(N_NODES + 127) / 128, 256>>>(x, W1);
    k_gather1<<<(N_NODES * 32 + 255) / 256, 256>>>(b1);

    k_gemm2<<<(N_NODES + 127) / 128, 256>>>();
    k_gather2<<<(N_NODES * 32 + 255) / 256, 256>>>(b2, b3, out);
}

// round 9
// speedup vs baseline: 1.5278x; 1.2129x over previous
#include <cuda_runtime.h>

#define N_NODES 50000
#define N_EDGES 800000
#define CH 128
#define OUT_CH 64
#define SCAN_B 1024
#define SCAN_NB ((N_NODES + SCAN_B - 1) / SCAN_B)   // 49
#define PAD_A 36
#define PAD_B 136
#define GEMM_SMEM ((128 * PAD_B + 128 * PAD_A) * 4)

// ---- persistent device scratch (no allocation allowed) ----
__device__ int   g_is64;
__device__ int   g_deg[N_NODES];
__device__ float g_dinv[N_NODES];
__device__ int   g_rowptr[N_NODES + 1];
__device__ int   g_fill[N_NODES];
__device__ int   g_bsum[64];
__device__ int   g_csr[N_EDGES];
__device__ __align__(16) float g_h1[(size_t)N_NODES * CH];
__device__ __align__(16) float g_hidden[(size_t)N_NODES * CH];
__device__ __align__(16) float g_h23[(size_t)N_NODES * CH];
__device__ __align__(16) float g_wc[CH * CH];

__device__ __forceinline__ int edge_at(const void* p, int i) {
    if (g_is64) return (int)(((const long long*)p)[i]);
    return ((const int*)p)[i];
}

// ---------------------------------------------------------------------------
__global__ void k_pre(const void* ei, const float* __restrict__ W2,
                      const float* __restrict__ W3) {
    int i = blockIdx.x * blockDim.x + threadIdx.x;
    if (i < N_NODES) { g_deg[i] = 1; g_fill[i] = 0; }
    if (i < CH * CH) {
        int k = i >> 7, c = i & 127;
        g_wc[i] = (c < OUT_CH) ? W2[k * OUT_CH + c] : W3[k * OUT_CH + (c - OUT_CH)];
    }
    if (i == 0) {
        const long long* p = (const long long*)ei;
        int ok64 = 1;
        for (int t = 0; t < 256; t++) {
            long long v = p[t];
            if (v < 0 || v >= N_NODES) { ok64 = 0; break; }
        }
        g_is64 = ok64;
    }
}

__global__ void k_deg(const void* __restrict__ ei) {
    int e = blockIdx.x * blockDim.x + threadIdx.x;
    if (e < N_EDGES) {
        int c = edge_at(ei, N_EDGES + e);
        if ((unsigned)c < N_NODES) atomicAdd(&g_deg[c], 1);
    }
}

// scan pass 1: per-block exclusive scan of (deg-1), block sums, fused dinv
__global__ void k_scan1() {
    __shared__ int wsum[32];
    int t = threadIdx.x;
    int i = blockIdx.x * SCAN_B + t;
    int lane = t & 31, wid = t >> 5;
    int v = 0;
    if (i < N_NODES) {
        int d = g_deg[i];
        v = d - 1;
        g_dinv[i] = rsqrtf((float)d);
    }
    int x = v;
    #pragma unroll
    for (int d = 1; d < 32; d <<= 1) {
        int y = __shfl_up_sync(0xffffffffu, x, d);
        if (lane >= d) x += y;
    }
    if (lane == 31) wsum[wid] = x;
    __syncthreads();
    if (wid == 0) {
        int y = wsum[lane];
        #pragma unroll
        for (int d = 1; d < 32; d <<= 1) {
            int z = __shfl_up_sync(0xffffffffu, y, d);
            if (lane >= d) y += z;
        }
        wsum[lane] = y;
    }
    __syncthreads();
    int base = (wid > 0) ? wsum[wid - 1] : 0;
    if (i < N_NODES) g_rowptr[i] = base + x - v;
    if (t == SCAN_B - 1) g_bsum[blockIdx.x] = wsum[31];
}

// scan pass 2 (fused): each block sums its prefix of block sums, adds offset
__global__ void k_scan3() {
    __shared__ int s_part[2];
    __shared__ int s_off;
    int t = threadIdx.x;
    if (t < 64) {
        int v = (t < blockIdx.x) ? g_bsum[t] : 0;
        #pragma unroll
        for (int d = 16; d; d >>= 1) v += __shfl_down_sync(0xffffffffu, v, d);
        if ((t & 31) == 0) s_part[t >> 5] = v;
    }
    __syncthreads();
    if (t == 0) s_off = s_part[0] + s_part[1];
    __syncthreads();
    int i = blockIdx.x * SCAN_B + t;
    if (i < N_NODES) g_rowptr[i] += s_off;
    if (i == 0) g_rowptr[N_NODES] = N_EDGES;
}

__global__ void k_fill(const void* __restrict__ ei) {
    int e = blockIdx.x * blockDim.x + threadIdx.x;
    if (e < N_EDGES) {
        int s = edge_at(ei, e);
        int c = edge_at(ei, N_EDGES + e);
        if ((unsigned)c < N_NODES && (unsigned)s < N_NODES) {
            int pos = g_rowptr[c] + atomicAdd(&g_fill[c], 1);
            if ((unsigned)pos < N_EDGES) g_csr[pos] = s;
        }
    }
}

// ---------------------------------------------------------------------------
// tf32 tensor-core GEMM: C[M,128] = A[M,128] @ B[128,128]
// block tile 128x128, 8 warps (4x2), warp tile 32x64, mma m16n8k8
__device__ __forceinline__ unsigned f2tf32(float f) {
    unsigned u;
    asm("cvt.rna.tf32.f32 %0, %1;" : "=r"(u) : "f"(f));
    return u;
}

__device__ __forceinline__ void mma_tf32(float& c0, float& c1, float& c2, float& c3,
                                         unsigned a0, unsigned a1, unsigned a2, unsigned a3,
                                         unsigned b0, unsigned b1) {
    asm volatile(
        "mma.sync.aligned.m16n8k8.row.col.f32.tf32.tf32.f32 "
        "{%0,%1,%2,%3}, {%4,%5,%6,%7}, {%8,%9}, {%0,%1,%2,%3};"
        : "+f"(c0), "+f"(c1), "+f"(c2), "+f"(c3)
        : "r"(a0), "r"(a1), "r"(a2), "r"(a3), "r"(b0), "r"(b1));
}

__device__ __forceinline__ void gemm_tf32_body(const float* __restrict__ A,
                                               const float* __restrict__ B,
                                               float* __restrict__ C, int M) {
    extern __shared__ unsigned smem_u[];
    unsigned* Bs = smem_u;                    // [128][PAD_B]
    unsigned* As = smem_u + 128 * PAD_B;      // [128][PAD_A]
    int tid = threadIdx.x;                    // 256
    int lane = tid & 31, wid = tid >> 5;
    int g = lane >> 2, t4 = lane & 3;
    int wm = wid >> 1, wn = wid & 1;
    int m_base = wm * 32, n_base = wn * 64;
    int m0 = blockIdx.x * 128;

    // load whole B (128x128), convert to tf32
    for (int idx = tid; idx < 128 * 32; idx += 256) {
        int k = idx >> 5, nq = (idx & 31) << 2;
        float4 v = *(const float4*)(B + (size_t)k * 128 + nq);
        unsigned* d = &Bs[k * PAD_B + nq];
        d[0] = f2tf32(v.x); d[1] = f2tf32(v.y);
        d[2] = f2tf32(v.z); d[3] = f2tf32(v.w);
    }

    float acc[2][8][4];
    #pragma unroll
    for (int mi = 0; mi < 2; mi++)
        #pragma unroll
        for (int ni = 0; ni < 8; ni++)
            #pragma unroll
            for (int q = 0; q < 4; q++) acc[mi][ni][q] = 0.f;

    for (int kc = 0; kc < 4; kc++) {          // K chunks of 32
        int k0c = kc * 32;
        __syncthreads();
        for (int idx = tid; idx < 128 * 8; idx += 256) {
            int m = idx >> 3, kq = (idx & 7) << 2;
            float4 v = make_float4(0.f, 0.f, 0.f, 0.f);
            if (m0 + m < M) v = *(const float4*)(A + (size_t)(m0 + m) * 128 + k0c + kq);
            unsigned* d = &As[m * PAD_A + kq];
            d[0] = f2tf32(v.x); d[1] = f2tf32(v.y);
            d[2] = f2tf32(v.z); d[3] = f2tf32(v.w);
        }
        __syncthreads();
        #pragma unroll
        for (int kk = 0; kk < 4; kk++) {      // 4 k-steps of 8
            int k0 = kk * 8;
            unsigned a[2][4];
            #pragma unroll
            for (int mi = 0; mi < 2; mi++) {
                int r0 = m_base + mi * 16 + g;
                a[mi][0] = As[r0 * PAD_A + k0 + t4];
                a[mi][1] = As[(r0 + 8) * PAD_A + k0 + t4];
                a[mi][2] = As[r0 * PAD_A + k0 + t4 + 4];
                a[mi][3] = As[(r0 + 8) * PAD_A + k0 + t4 + 4];
            }
            unsigned b[8][2];
            int K0 = k0c + k0;
            #pragma unroll
            for (int ni = 0; ni < 8; ni++) {
                int cbase = n_base + ni * 8 + g;
                b[ni][0] = Bs[(K0 + t4) * PAD_B + cbase];
                b[ni][1] = Bs[(K0 + t4 + 4) * PAD_B + cbase];
            }
            #pragma unroll
            for (int mi = 0; mi < 2; mi++)
                #pragma unroll
                for (int ni = 0; ni < 8; ni++)
                    mma_tf32(acc[mi][ni][0], acc[mi][ni][1], acc[mi][ni][2], acc[mi][ni][3],
                             a[mi][0], a[mi][1], a[mi][2], a[mi][3],
                             b[ni][0], b[ni][1]);
        }
    }

    #pragma unroll
    for (int mi = 0; mi < 2; mi++) {
        int r0 = m0 + m_base + mi * 16 + g;
        int r1 = r0 + 8;
        #pragma unroll
        for (int ni = 0; ni < 8; ni++) {
            int col = n_base + ni * 8 + 2 * t4;
            if (r0 < M)
                *(float2*)(C + (size_t)r0 * 128 + col) = make_float2(acc[mi][ni][0], acc[mi][ni][1]);
            if (r1 < M)
                *(float2*)(C + (size_t)r1 * 128 + col) = make_float2(acc[mi][ni][2], acc[mi][ni][3]);
        }
    }
}

__global__ void k_gemm1(const float* __restrict__ A, const float* __restrict__ B) {
    gemm_tf32_body(A, B, g_h1, N_NODES);
}
__global__ void k_gemm2() {
    gemm_tf32_body(g_hidden, g_wc, g_h23, N_NODES);
}

// ---------------------------------------------------------------------------
// warp-per-node gather, unroll-2 for MLP
__device__ __forceinline__ float4 gather_row(const float* __restrict__ h, int node,
                                             int lane) {
    int start = __ldg(&g_rowptr[node]);
    int end   = __ldg(&g_rowptr[node + 1]);
    float4 a0 = make_float4(0.f, 0.f, 0.f, 0.f);
    float4 a1 = make_float4(0.f, 0.f, 0.f, 0.f);
    int j = start;
    for (; j + 1 < end; j += 2) {
        int s0 = __ldg(&g_csr[j]);
        int s1 = __ldg(&g_csr[j + 1]);
        float w0 = __ldg(&g_dinv[s0]);
        float w1 = __ldg(&g_dinv[s1]);
        float4 v0 = *(const float4*)(h + (size_t)s0 * CH + lane * 4);
        float4 v1 = *(const float4*)(h + (size_t)s1 * CH + lane * 4);
        a0.x = fmaf(w0, v0.x, a0.x); a1.x = fmaf(w1, v1.x, a1.x);
        a0.y = fmaf(w0, v0.y, a0.y); a1.y = fmaf(w1, v1.y, a1.y);
        a0.z = fmaf(w0, v0.z, a0.z); a1.z = fmaf(w1, v1.z, a1.z);
        a0.w = fmaf(w0, v0.w, a0.w); a1.w = fmaf(w1, v1.w, a1.w);
    }
    if (j < end) {
        int s0 = __ldg(&g_csr[j]);
        float w0 = __ldg(&g_dinv[s0]);
        float4 v0 = *(const float4*)(h + (size_t)s0 * CH + lane * 4);
        a0.x = fmaf(w0, v0.x, a0.x);
        a0.y = fmaf(w0, v0.y, a0.y);
        a0.z = fmaf(w0, v0.z, a0.z);
        a0.w = fmaf(w0, v0.w, a0.w);
    }
    a0.x += a1.x; a0.y += a1.y; a0.z += a1.z; a0.w += a1.w;
    return a0;
}

__global__ void k_gather1(const float* __restrict__ b1) {
    int gtid = blockIdx.x * blockDim.x + threadIdx.x;
    int node = gtid >> 5;
    int lane = gtid & 31;
    if (node >= N_NODES) return;
    float4 acc = gather_row(g_h1, node, lane);
    float me = __ldg(&g_dinv[node]);
    float m2 = me * me;
    float4 self = *(const float4*)(g_h1 + (size_t)node * CH + lane * 4);
    float4 bb   = *(const float4*)(b1 + lane * 4);
    float4 o;
    o.x = fmaxf(fmaf(acc.x, me, fmaf(self.x, m2, bb.x)), 0.f);
    o.y = fmaxf(fmaf(acc.y, me, fmaf(self.y, m2, bb.y)), 0.f);
    o.z = fmaxf(fmaf(acc.z, me, fmaf(self.z, m2, bb.z)), 0.f);
    o.w = fmaxf(fmaf(acc.w, me, fmaf(self.w, m2, bb.w)), 0.f);
    *(float4*)(g_hidden + (size_t)node * CH + lane * 4) = o;
}

__global__ void k_gather2(const float* __restrict__ b2, const float* __restrict__ b3,
                          float* __restrict__ out) {
    int gtid = blockIdx.x * blockDim.x + threadIdx.x;
    int node = gtid >> 5;
    int lane = gtid & 31;
    if (node >= N_NODES) return;
    float4 acc = gather_row(g_h23, node, lane);
    float me = __ldg(&g_dinv[node]);
    float m2 = me * me;
    float4 self = *(const float4*)(g_h23 + (size_t)node * CH + lane * 4);
    const float* bias = (lane < 16) ? (b2 + lane * 4) : (b3 + (lane - 16) * 4);
    float4 bb = *(const float4*)bias;
    float4 o;
    o.x = fmaxf(fmaf(acc.x, me, fmaf(self.x, m2, bb.x)), 0.f);
    o.y = fmaxf(fmaf(acc.y, me, fmaf(self.y, m2, bb.y)), 0.f);
    o.z = fmaxf(fmaf(acc.z, me, fmaf(self.z, m2, bb.z)), 0.f);
    o.w = fmaxf(fmaf(acc.w, me, fmaf(self.w, m2, bb.w)), 0.f);
    float* dst = (lane < 16)
        ? (out + (size_t)node * OUT_CH + lane * 4)
        : (out + (size_t)N_NODES * OUT_CH + (size_t)node * OUT_CH + (lane - 16) * 4);
    *(float4*)dst = o;
}

// ---------------------------------------------------------------------------
extern "C" void kernel_launch(void* const* d_in, const int* in_sizes, int n_in,
                              void* d_out, int out_size) {
    const float* x  = (const float*)d_in[0];
    const void*  ei = d_in[1];
    const float* W1 = (const float*)d_in[2];
    const float* b1 = (const float*)d_in[3];
    const float* W2 = (const float*)d_in[4];
    const float* b2 = (const float*)d_in[5];
    const float* W3 = (const float*)d_in[6];
    const float* b3 = (const float*)d_in[7];
    float* out = (float*)d_out;

    cudaFuncSetAttribute(k_gemm1, cudaFuncAttributeMaxDynamicSharedMemorySize, GEMM_SMEM);
    cudaFuncSetAttribute(k_gemm2, cudaFuncAttributeMaxDynamicSharedMemorySize, GEMM_SMEM);

    k_pre<<<(N_NODES + 255) / 256, 256>>>(ei, W2, W3);
    k_deg<<<(N_EDGES + 255) / 256, 256>>>(ei);
    k_scan1<<<SCAN_NB, SCAN_B>>>();
    k_scan3<<<SCAN_NB, SCAN_B>>>();
    k_fill<<<(N_EDGES + 255) / 256, 256>>>(ei);

    k_gemm1<<<(N_NODES + 127) / 128, 256, GEMM_SMEM>>>(x, W1);
    k_gather1<<<(N_NODES * 32 + 255) / 256, 256>>>(b1);

    k_gemm2<<<(N_NODES + 127) / 128, 256, GEMM_SMEM>>>();
    k_gather2<<<(N_NODES * 32 + 255) / 256, 256>>>(b2, b3, out);
}